// round 15
// baseline (speedup 1.0000x reference)
#include <cuda_runtime.h>

#define BB 16
#define HH 512
#define WW 512
#define PL (HH*WW)            // 262144 elems per channel plane
#define NPIX (BB*PL)          // 4194304 pixels per input set
#define P1_BLOCKS 2048        // pass1 blocks (8 x 8 x 32)
#define P2_BLOCKS 512
#define CAP (1<<22)           // candidate capacity (4M)
#define CAND_T 0.0165f        // conservative: 0.001*mean <= 0.016 since ssd < 16

// Static scratch
__device__ float    g_part1[P1_BLOCKS];
__device__ float    g_part2[P2_BLOCKS];
__device__ unsigned g_cand_idx[CAP];   // bit31 = which (0=src,1=tgt), low = pixel idx
__device__ float    g_cand_val[CAP];
__device__ unsigned g_cand_n;
__device__ unsigned g_done2;
__device__ float    g_sumS, g_sumT;

__device__ __forceinline__ int clampi(int v, int lo, int hi) {
    return min(max(v, lo), hi);
}

// diff^2 at clamped center (cy,cx).
// Association: d = ((pa + qb) + rc) - sd. This EXACT tree is used by every
// path (fast float2, scalar boundary, pass2 recompute) so the candidate
// threshold test is bit-consistent between passes.
__device__ __forceinline__ float diff2_at(const float* __restrict__ I0,
                                          const float* __restrict__ I1,
                                          const float* __restrict__ I2,
                                          int cy, int cx) {
    int ym = max(cy - 2, 0), yp = min(cy + 2, HH - 1);
    int xm = max(cx - 2, 0), xp = min(cx + 2, WW - 1);
    int ia = cy * WW + xm;   // (y,   x-2)
    int ib = yp * WW + xp;   // (y+2, x+2)
    int ic = yp * WW + xm;   // (y+2, x-2)
    int id = ym * WW + cx;   // (y-2, x)
    float pa = I0[ia] - I1[ia];
    float qb = I0[ib] - I2[ib];
    float rc = I1[ic] + I2[ic];
    float sd = I0[id] + I2[id];
    float d = ((pa + qb) + rc) - sd;
    return d * d;
}

// ssd at pixel (y,x) — bit-exact replica of pass1's 3-stage order.
__device__ float ssd_at(const float* __restrict__ img, int y, int x) {
    const float* I0 = img;
    const float* I1 = img + PL;
    const float* I2 = img + 2 * PL;
    float acc = 0.f;
    #pragma unroll
    for (int dy = -2; dy <= 2; dy++) {
        int yy = clampi(y + dy, 0, HH - 1);
        float hs = 0.f;
        #pragma unroll
        for (int dx = -2; dx <= 2; dx++) {
            int xx = clampi(x + dx, 0, WW - 1);
            hs += diff2_at(I0, I1, I2, yy, xx);
        }
        acc += hs;
    }
    return acc * (1.0f / 25.0f);
}

// ---------------------------------------------------------------------------
// Pass 1: tile 64x64, block (32,16). Fully-interior blocks run a branch-free
// unrolled path with 3 incrementing row pointers; boundary blocks keep the
// general per-row path. grid (8, 8, 32): z = which*16 + batch.
// ---------------------------------------------------------------------------
__global__ __launch_bounds__(512, 3) void k_pass1(const float* __restrict__ src,
                                                  const float* __restrict__ tgt) {
    __shared__ float s_d2[68][72];   // diff^2, halo cols 0..67 (even stride)
    __shared__ float s_h[68][66];    // horizontal 5-sums, cols 0..63
    __shared__ float s_red[16];

    const int tz    = blockIdx.z;
    const int which = tz >> 4;       // 0 = source, 1 = target
    const int b     = tz & 15;
    const float* img = (which ? tgt : src) + (size_t)b * 4 * PL;
    const float* __restrict__ I0 = img;
    const float* __restrict__ I1 = img + PL;
    const float* __restrict__ I2 = img + 2 * PL;

    const int bx = blockIdx.x, by = blockIdx.y;
    const int tx0 = bx * 64;
    const int ty0 = by * 64;
    const int lane = threadIdx.x, wid = threadIdx.y;
    const int t   = wid * 32 + lane;
    const bool x_int = (bx >= 1) && (bx <= 6);
    const bool y_int = (by >= 1) && (by <= 6);

    // ---- Stage A: diff^2 over the 68(row) x 68(col) halo region ----
    // halo pixel (r,c) = image pixel (ty0-2+r, tx0-2+c), edge-clamped.
    if (x_int && y_int) {
        const int c = 2 * lane;
        // Row-grouped base pointers for halo row r = wid:
        //  pA -> image row (ty0-2+r), col tx0-4+c  : P taps (I0,I1 @ x-2)
        //  pB -> image row (ty0+r),   col tx0-4+c  : R taps @+0, Q taps @+4
        //  pD -> image row (ty0-4+r), col tx0-2+c  : S taps (I0,I2 @ x)
        const float* pA = img + (size_t)(ty0 - 2 + wid) * WW + (tx0 - 4 + c);
        const float* pB = img + (size_t)(ty0 + wid) * WW + (tx0 - 4 + c);
        const float* pD = img + (size_t)(ty0 - 4 + wid) * WW + (tx0 - 2 + c);
        const bool tail = (lane < 2);   // halo cols 64..67 via +64 offsets

        auto do_row = [&](int r, const float* qA, const float* qB,
                          const float* qD) {
            float2 a0 = *(const float2*)(qA);
            float2 a1 = *(const float2*)(qA + PL);
            float2 b0 = *(const float2*)(qB + 4);
            float2 b2 = *(const float2*)(qB + 4 + 2 * PL);
            float2 c1 = *(const float2*)(qB + PL);
            float2 c2 = *(const float2*)(qB + 2 * PL);
            float2 d0 = *(const float2*)(qD);
            float2 d2v = *(const float2*)(qD + 2 * PL);
            float2 o;
            {
                float pa = a0.x - a1.x, qb = b0.x - b2.x;
                float rc = c1.x + c2.x, sd = d0.x + d2v.x;
                float d = ((pa + qb) + rc) - sd;
                o.x = d * d;
            }
            {
                float pa = a0.y - a1.y, qb = b0.y - b2.y;
                float rc = c1.y + c2.y, sd = d0.y + d2v.y;
                float d = ((pa + qb) + rc) - sd;
                o.y = d * d;
            }
            *(float2*)&s_d2[r][c] = o;
            if (tail) {
                float2 ta0 = *(const float2*)(qA + 64);
                float2 ta1 = *(const float2*)(qA + 64 + PL);
                float2 tb0 = *(const float2*)(qB + 68);
                float2 tb2 = *(const float2*)(qB + 68 + 2 * PL);
                float2 tc1 = *(const float2*)(qB + 64 + PL);
                float2 tc2 = *(const float2*)(qB + 64 + 2 * PL);
                float2 td0 = *(const float2*)(qD + 64);
                float2 td2 = *(const float2*)(qD + 64 + 2 * PL);
                float2 ot;
                {
                    float pa = ta0.x - ta1.x, qb = tb0.x - tb2.x;
                    float rc = tc1.x + tc2.x, sd = td0.x + td2.x;
                    float d = ((pa + qb) + rc) - sd;
                    ot.x = d * d;
                }
                {
                    float pa = ta0.y - ta1.y, qb = tb0.y - tb2.y;
                    float rc = tc1.y + tc2.y, sd = td0.y + td2.y;
                    float d = ((pa + qb) + rc) - sd;
                    ot.y = d * d;
                }
                *(float2*)&s_d2[r][c + 64] = ot;
            }
        };

        #pragma unroll
        for (int k = 0; k < 4; k++) {
            do_row(wid + 16 * k, pA, pB, pD);
            pA += 16 * WW; pB += 16 * WW; pD += 16 * WW;
        }
        if (wid < 4) do_row(wid + 64, pA, pB, pD);
    } else {
        for (int r = wid; r < 68; r += 16) {
            const bool rowfast = x_int && (ty0 - 4 + r >= 0) && (ty0 + r <= HH - 1);
            if (rowfast) {
                const float* rowA = img + (ty0 - 2 + r) * WW;
                const float* rowB = img + (ty0 + r) * WW;
                const float* rowD = img + (ty0 - 4 + r) * WW;
                int c = 2 * lane;
                {
                    const float* pA = rowA + tx0 - 4 + c;
                    const float* pB = rowB + tx0 + c;
                    const float* pC = rowB + tx0 - 4 + c;
                    const float* pD = rowD + tx0 - 2 + c;
                    float2 a0 = *(const float2*)(pA);
                    float2 a1 = *(const float2*)(pA + PL);
                    float2 b0 = *(const float2*)(pB);
                    float2 b2 = *(const float2*)(pB + 2 * PL);
                    float2 c1 = *(const float2*)(pC + PL);
                    float2 c2 = *(const float2*)(pC + 2 * PL);
                    float2 d0 = *(const float2*)(pD);
                    float2 d2 = *(const float2*)(pD + 2 * PL);
                    float2 o;
                    {
                        float pa = a0.x - a1.x, qb = b0.x - b2.x;
                        float rc = c1.x + c2.x, sd = d0.x + d2.x;
                        float d = ((pa + qb) + rc) - sd;
                        o.x = d * d;
                    }
                    {
                        float pa = a0.y - a1.y, qb = b0.y - b2.y;
                        float rc = c1.y + c2.y, sd = d0.y + d2.y;
                        float d = ((pa + qb) + rc) - sd;
                        o.y = d * d;
                    }
                    *(float2*)&s_d2[r][c] = o;
                }
                if (lane < 2) {
                    int ct = 64 + 2 * lane;
                    const float* pA = rowA + tx0 - 4 + ct;
                    const float* pB = rowB + tx0 + ct;
                    const float* pC = rowB + tx0 - 4 + ct;
                    const float* pD = rowD + tx0 - 2 + ct;
                    float2 a0 = *(const float2*)(pA);
                    float2 a1 = *(const float2*)(pA + PL);
                    float2 b0 = *(const float2*)(pB);
                    float2 b2 = *(const float2*)(pB + 2 * PL);
                    float2 c1 = *(const float2*)(pC + PL);
                    float2 c2 = *(const float2*)(pC + 2 * PL);
                    float2 d0 = *(const float2*)(pD);
                    float2 d2 = *(const float2*)(pD + 2 * PL);
                    float2 o;
                    {
                        float pa = a0.x - a1.x, qb = b0.x - b2.x;
                        float rc = c1.x + c2.x, sd = d0.x + d2.x;
                        float d = ((pa + qb) + rc) - sd;
                        o.x = d * d;
                    }
                    {
                        float pa = a0.y - a1.y, qb = b0.y - b2.y;
                        float rc = c1.y + c2.y, sd = d0.y + d2.y;
                        float d = ((pa + qb) + rc) - sd;
                        o.y = d * d;
                    }
                    *(float2*)&s_d2[r][ct] = o;
                }
            } else {
                int cy = clampi(ty0 - 2 + r, 0, HH - 1);
                #pragma unroll
                for (int cc = lane; cc < 68; cc += 32) {
                    int cx = clampi(tx0 - 2 + cc, 0, WW - 1);
                    s_d2[r][cc] = diff2_at(I0, I1, I2, cy, cx);
                }
            }
        }
    }
    __syncthreads();

    // ---- Stage B: horizontal 5-sum (68 rows x 64 cols) ----
    if (x_int) {
        const int c = 2 * lane;
        auto do_b = [&](int r) {
            float2 v0 = *(const float2*)&s_d2[r][c];
            float2 v1 = *(const float2*)&s_d2[r][c + 2];
            float2 v2 = *(const float2*)&s_d2[r][c + 4];
            float2 h;
            h.x = ((((v0.x + v0.y) + v1.x) + v1.y) + v2.x);
            h.y = ((((v0.y + v1.x) + v1.y) + v2.x) + v2.y);
            *(float2*)&s_h[r][c] = h;
        };
        #pragma unroll
        for (int k = 0; k < 4; k++) do_b(wid + 16 * k);
        if (wid < 4) do_b(wid + 64);
    } else {
        for (int i = t; i < 68 * 64; i += 512) {
            int r = i >> 6, c = i & 63;
            int gx = tx0 + c;
            float s = 0.f;
            #pragma unroll
            for (int dx = -2; dx <= 2; dx++) {
                int sx = clampi(gx + dx, 0, WW - 1) - tx0 + 2;
                s += s_d2[r][sx];
            }
            s_h[r][c] = s;
        }
    }
    __syncthreads();

    // ---- Stage C: vertical 5-sum, accumulate, record candidates ----
    float lsum = 0.f;
    const int c0 = 2 * lane;
    #pragma unroll
    for (int k = 0; k < 4; k++) {
        int y  = wid + k * 16;
        int gy = ty0 + y;
        float sx_, sy_;
        const bool rowfastC = y_int || ((gy - 2 >= 0) && (gy + 2 <= HH - 1));
        if (rowfastC) {
            float2 h0 = *(const float2*)&s_h[y][c0];
            float2 h1 = *(const float2*)&s_h[y + 1][c0];
            float2 h2 = *(const float2*)&s_h[y + 2][c0];
            float2 h3 = *(const float2*)&s_h[y + 3][c0];
            float2 h4 = *(const float2*)&s_h[y + 4][c0];
            sx_ = ((((h0.x + h1.x) + h2.x) + h3.x) + h4.x);
            sy_ = ((((h0.y + h1.y) + h2.y) + h3.y) + h4.y);
        } else {
            sx_ = 0.f; sy_ = 0.f;
            #pragma unroll
            for (int dy = -2; dy <= 2; dy++) {
                int sy = clampi(gy + dy, 0, HH - 1) - ty0 + 2;
                sx_ += s_h[sy][c0];
                sy_ += s_h[sy][c0 + 1];
            }
        }
        sx_ *= (1.0f / 25.0f);
        sy_ *= (1.0f / 25.0f);
        lsum += sx_ + sy_;
        if (sx_ < CAND_T) {
            unsigned slot = atomicAdd(&g_cand_n, 1u);
            if (slot < CAP) {
                g_cand_idx[slot] = ((unsigned)which << 31)
                                 | (unsigned)(b * PL + gy * WW + tx0 + c0);
                g_cand_val[slot] = sx_;
            }
        }
        if (sy_ < CAND_T) {
            unsigned slot = atomicAdd(&g_cand_n, 1u);
            if (slot < CAP) {
                g_cand_idx[slot] = ((unsigned)which << 31)
                                 | (unsigned)(b * PL + gy * WW + tx0 + c0 + 1);
                g_cand_val[slot] = sy_;
            }
        }
    }

    // block reduction -> per-block partial
    #pragma unroll
    for (int o = 16; o; o >>= 1) lsum += __shfl_down_sync(0xffffffffu, lsum, o);
    if (lane == 0) s_red[wid] = lsum;
    __syncthreads();
    if (t < 16) {
        float v = s_red[t];
        #pragma unroll
        for (int o = 8; o; o >>= 1) v += __shfl_down_sync(0xffffu, v, o);
        if (t == 0) g_part1[tz * 64 + by * 8 + bx] = v;
    }
}

// ---------------------------------------------------------------------------
// p2red: one block reduces the 2048 pass1 partials -> g_sumS, g_sumT.
// Partials: indices 0..1023 = source (tz 0..15), 1024..2047 = target.
// ---------------------------------------------------------------------------
__global__ __launch_bounds__(256) void k_p2red() {
    const float4* p4 = (const float4*)g_part1;
    float accS = 0.f, accT = 0.f;
    {
        float4 a = p4[threadIdx.x];
        accS = (a.x + a.y) + (a.z + a.w);
        float4 bq = p4[threadIdx.x + 256];
        accT = (bq.x + bq.y) + (bq.z + bq.w);
    }
    #pragma unroll
    for (int o = 16; o; o >>= 1) {
        accS += __shfl_down_sync(0xffffffffu, accS, o);
        accT += __shfl_down_sync(0xffffffffu, accT, o);
    }
    __shared__ float sS[8], sT[8];
    if ((threadIdx.x & 31) == 0) {
        sS[threadIdx.x >> 5] = accS; sT[threadIdx.x >> 5] = accT;
    }
    __syncthreads();
    if (threadIdx.x == 0) {
        float fS = 0.f, fT = 0.f;
        #pragma unroll
        for (int j = 0; j < 8; j++) { fS += sS[j]; fT += sT[j]; }
        g_sumS = fS; g_sumT = fT;
    }
}

// ---------------------------------------------------------------------------
// Pass 2: loss from candidates only (unclipped pairs contribute exactly 0:
// exp(-x/(0.25x)) == exp(-4) bit-exactly). Last block reduces partials,
// writes out, resets state for graph replay.
// ---------------------------------------------------------------------------
__global__ __launch_bounds__(256) void k_pass2(const float* __restrict__ src,
                                               const float* __restrict__ tgt,
                                               float* __restrict__ out) {
    const float sumS = g_sumS, sumT = g_sumT;
    const float meanS = sumS * (1.0f / (float)NPIX);
    const float meanT = sumT * (1.0f / (float)NPIX);
    const unsigned cn = g_cand_n;
    const bool full = (meanS < CAND_T) || (meanT < CAND_T) || (cn > CAP);
    const unsigned n = cn > CAP ? CAP : cn;

    const float mv_s = (float)((double)sumS / (4.0 * (double)NPIX));
    const float mv_t = (float)((double)sumT / (4.0 * (double)NPIX));
    const float lo_s = mv_s * 0.001f, hi_s = mv_s * 1000.0f;
    const float lo_t = mv_t * 0.001f, hi_t = mv_t * 1000.0f;

    const int tid = blockIdx.x * 256 + threadIdx.x;
    const int stride = gridDim.x * 256;
    float acc = 0.f;

    if (!full) {
        for (unsigned e = tid; e < n; e += stride) {
            unsigned rec = g_cand_idx[e];
            float val = g_cand_val[e];
            int w = rec >> 31;
            unsigned idx = rec & 0x7fffffffu;
            int b = idx / PL; int rem = idx - b * PL;
            int y = rem / WW; int x = rem - y * WW;
            const float* oimg = (w ? src : tgt) + (size_t)b * 4 * PL;
            float other = ssd_at(oimg, y, x);
            float a, bt;
            if (w == 0) { a = val; bt = other; }
            else {
                a = other; bt = val;
                // skip iff source side is itself a candidate: that entry
                // computed the whole pair (prevents double count).
                if (a < CAND_T) continue;
            }
            float va = fminf(fmaxf(a  * 0.25f, lo_s), hi_s);
            float vb = fminf(fmaxf(bt * 0.25f, lo_t), hi_t);
            float d = __expf(-a / va) - __expf(-bt / vb);
            acc += d * d;
        }
    } else {
        // never-taken safety path: full recompute of both ssd fields
        for (long i = tid; i < (long)NPIX; i += stride) {
            int b = (int)(i / PL); int rem = (int)(i - (long)b * PL);
            int y = rem / WW; int x = rem - y * WW;
            float a  = ssd_at(src + (size_t)b * 4 * PL, y, x);
            float bt = ssd_at(tgt + (size_t)b * 4 * PL, y, x);
            float va = fminf(fmaxf(a  * 0.25f, lo_s), hi_s);
            float vb = fminf(fmaxf(bt * 0.25f, lo_t), hi_t);
            float d = __expf(-a / va) - __expf(-bt / vb);
            acc += d * d;
        }
    }

    __shared__ float s_red[8];
    __shared__ int   s_last;
    #pragma unroll
    for (int o = 16; o; o >>= 1) acc += __shfl_down_sync(0xffffffffu, acc, o);
    if ((threadIdx.x & 31) == 0) s_red[threadIdx.x >> 5] = acc;
    __syncthreads();
    if (threadIdx.x < 8) {
        float v = s_red[threadIdx.x];
        #pragma unroll
        for (int o = 4; o; o >>= 1) v += __shfl_down_sync(0xffu, v, o);
        if (threadIdx.x == 0) g_part2[blockIdx.x] = v;
    }

    if (threadIdx.x == 0) {
        __threadfence();
        unsigned v = atomicAdd(&g_done2, 1u);
        s_last = (v == P2_BLOCKS - 1);
    }
    __syncthreads();
    if (s_last) {
        float v = g_part2[threadIdx.x] + g_part2[threadIdx.x + 256];
        #pragma unroll
        for (int o = 16; o; o >>= 1) v += __shfl_down_sync(0xffffffffu, v, o);
        __shared__ float s_f[8];
        if ((threadIdx.x & 31) == 0) s_f[threadIdx.x >> 5] = v;
        __syncthreads();
        if (threadIdx.x == 0) {
            float tot = 0.f;
            #pragma unroll
            for (int j = 0; j < 8; j++) tot += s_f[j];
            out[0] = (float)((double)tot / (3.0 * (double)NPIX));
            g_done2 = 0;
            g_cand_n = 0;   // reset for next graph replay
        }
    }
}

extern "C" void kernel_launch(void* const* d_in, const int* in_sizes, int n_in,
                              void* d_out, int out_size) {
    const float* src = (const float*)d_in[0];
    const float* tgt = (const float*)d_in[1];
    float* out = (float*)d_out;

    dim3 grid(8, 8, 32), block(32, 16);
    k_pass1<<<grid, block>>>(src, tgt);
    k_p2red<<<1, 256>>>();
    k_pass2<<<P2_BLOCKS, 256>>>(src, tgt, out);
}

// round 16
// speedup vs baseline: 1.3265x; 1.3265x over previous
#include <cuda_runtime.h>

#define BB 16
#define HH 512
#define WW 512
#define PL (HH*WW)            // 262144 elems per channel plane
#define NPIX (BB*PL)          // 4194304 pixels per input set
#define P1_BLOCKS 2048        // pass1 blocks (4 x 16 x 32)
#define P2_BLOCKS 512
#define CAP (1<<22)           // candidate capacity (4M)
#define CAND_T 0.0165f        // conservative: 0.001*mean <= 0.016 since ssd < 16

// Static scratch
__device__ float    g_part1[P1_BLOCKS];
__device__ float    g_part2[P2_BLOCKS];
__device__ unsigned g_cand_idx[CAP];   // bit31 = which (0=src,1=tgt), low = pixel idx
__device__ float    g_cand_val[CAP];
__device__ unsigned g_cand_n;
__device__ unsigned g_done2;
__device__ float    g_sumS, g_sumT;

__device__ __forceinline__ int clampi(int v, int lo, int hi) {
    return min(max(v, lo), hi);
}

// diff^2 at clamped center (cy,cx).
// Association: d = ((pa + qb) + rc) - sd. This EXACT tree is used by every
// path (pass1 fast/cleanup, pass2 recompute) so the candidate threshold test
// is bit-consistent between passes.
__device__ __forceinline__ float diff2_at(const float* __restrict__ I0,
                                          const float* __restrict__ I1,
                                          const float* __restrict__ I2,
                                          int cy, int cx) {
    int ym = max(cy - 2, 0), yp = min(cy + 2, HH - 1);
    int xm = max(cx - 2, 0), xp = min(cx + 2, WW - 1);
    int ia = cy * WW + xm;   // (y,   x-2)
    int ib = yp * WW + xp;   // (y+2, x+2)
    int ic = yp * WW + xm;   // (y+2, x-2)
    int id = ym * WW + cx;   // (y-2, x)
    float pa = I0[ia] - I1[ia];
    float qb = I0[ib] - I2[ib];
    float rc = I1[ic] + I2[ic];
    float sd = I0[id] + I2[id];
    float d = ((pa + qb) + rc) - sd;
    return d * d;
}

// ssd at pixel (y,x) — bit-exact replica of pass1's staged op order.
__device__ float ssd_at(const float* __restrict__ img, int y, int x) {
    const float* I0 = img;
    const float* I1 = img + PL;
    const float* I2 = img + 2 * PL;
    float acc = 0.f;
    #pragma unroll
    for (int dy = -2; dy <= 2; dy++) {
        int yy = clampi(y + dy, 0, HH - 1);
        float hs = 0.f;
        #pragma unroll
        for (int dx = -2; dx <= 2; dx++) {
            int xx = clampi(x + dx, 0, WW - 1);
            hs += diff2_at(I0, I1, I2, yy, xx);
        }
        acc += hs;
    }
    return acc * (1.0f / 25.0f);
}

// ---------------------------------------------------------------------------
// Pass 1: tile 128 (w) x 32 (h), block (32,8) = 256 threads.
// Stage A: aligned LDG.128 + lane shuffles; y-clamps folded into row pointers
// (same clamp semantics as diff2_at), so ONE fast path serves all blocks.
// x-edge halo cols (12 per tile) handled by a scalar clamped cleanup.
// Stage B+C fused: h rows in registers, s_h eliminated, one barrier total.
// grid (4, 16, 32): z = which*16 + batch.
// ---------------------------------------------------------------------------
__global__ __launch_bounds__(256) void k_pass1(const float* __restrict__ src,
                                               const float* __restrict__ tgt) {
    // s_d2[r][j]: d2 of image pixel (ty0-2+r, tx0-4+j), j in [2,134) valid.
    __shared__ __align__(16) float s_d2[36][136];
    __shared__ float s_red[8];

    const int tz    = blockIdx.z;
    const int which = tz >> 4;       // 0 = source, 1 = target
    const int b     = tz & 15;
    const float* img = (which ? tgt : src) + (size_t)b * 4 * PL;
    const float* __restrict__ I0 = img;
    const float* __restrict__ I1 = img + PL;
    const float* __restrict__ I2 = img + 2 * PL;

    const int bx = blockIdx.x, by = blockIdx.y;
    const int tx0 = bx * 128;
    const int ty0 = by * 32;
    const int lane = threadIdx.x, wid = threadIdx.y;
    const int t   = wid * 32 + lane;

    // ---- Stage A fast: lanes 1..30 produce image cols [tx0+4, tx0+124) ----
    {
        const int C = tx0 + 4 * lane;   // aligned float4 base column
        for (int r = wid; r < 36; r += 8) {
            int iy = ty0 - 2 + r;
            int cy = clampi(iy, 0, HH - 1);
            int ym = max(cy - 2, 0);
            int yp = min(cy + 2, HH - 1);
            const float* pR = I0 + cy * WW + C;
            const float* pD = I0 + ym * WW + C;
            const float* pU = I0 + yp * WW + C;

            float4 v0r = *(const float4*)(pR);
            float4 v1r = *(const float4*)(pR + PL);
            float4 v0d = *(const float4*)(pD);
            float4 v2d = *(const float4*)(pD + 2 * PL);
            float4 v0u = *(const float4*)(pU);
            float4 v1u = *(const float4*)(pU + PL);
            float4 v2u = *(const float4*)(pU + 2 * PL);

            // neighbor words via shuffle (prev lane's .z/.w, next lane's .x/.y)
            float p0z = __shfl_up_sync(0xffffffffu, v0r.z, 1);
            float p0w = __shfl_up_sync(0xffffffffu, v0r.w, 1);
            float p1z = __shfl_up_sync(0xffffffffu, v1r.z, 1);
            float p1w = __shfl_up_sync(0xffffffffu, v1r.w, 1);
            float u1z = __shfl_up_sync(0xffffffffu, v1u.z, 1);
            float u1w = __shfl_up_sync(0xffffffffu, v1u.w, 1);
            float u2z = __shfl_up_sync(0xffffffffu, v2u.z, 1);
            float u2w = __shfl_up_sync(0xffffffffu, v2u.w, 1);
            float n0x = __shfl_down_sync(0xffffffffu, v0u.x, 1);
            float n0y = __shfl_down_sync(0xffffffffu, v0u.y, 1);
            float n2x = __shfl_down_sync(0xffffffffu, v2u.x, 1);
            float n2y = __shfl_down_sync(0xffffffffu, v2u.y, 1);

            // taps per component k (out col C+k):
            // pa = I0-I1 @(cy, c-2); qb = I0-I2 @(yp, c+2);
            // rc = I1+I2 @(yp, c-2); sd = I0+I2 @(ym, c)
            float pa0 = p0z   - p1z,   pa1 = p0w   - p1w;
            float pa2 = v0r.x - v1r.x, pa3 = v0r.y - v1r.y;
            float qb0 = v0u.z - v2u.z, qb1 = v0u.w - v2u.w;
            float qb2 = n0x   - n2x,   qb3 = n0y   - n2y;
            float rc0 = u1z   + u2z,   rc1 = u1w   + u2w;
            float rc2 = v1u.x + v2u.x, rc3 = v1u.y + v2u.y;
            float sd0 = v0d.x + v2d.x, sd1 = v0d.y + v2d.y;
            float sd2 = v0d.z + v2d.z, sd3 = v0d.w + v2d.w;

            float d0 = ((pa0 + qb0) + rc0) - sd0;
            float d1 = ((pa1 + qb1) + rc1) - sd1;
            float d2 = ((pa2 + qb2) + rc2) - sd2;
            float d3 = ((pa3 + qb3) + rc3) - sd3;

            if (lane >= 1 && lane <= 30) {
                *(float4*)&s_d2[r][4 * lane + 4] =
                    make_float4(d0 * d0, d1 * d1, d2 * d2, d3 * d3);
            }
        }
    }

    // ---- Stage A cleanup: j in [2,8) and [128,134), 12 cols x 36 rows ----
    for (int i = t; i < 432; i += 256) {
        int r = i / 12;
        int m = i - r * 12;
        int j = (m < 6) ? (2 + m) : (122 + m);   // 2..7 or 128..133
        int cy = clampi(ty0 - 2 + r, 0, HH - 1);
        int cx = clampi(tx0 - 4 + j, 0, WW - 1);
        s_d2[r][j] = diff2_at(I0, I1, I2, cy, cx);
    }
    __syncthreads();

    // ---- Fused B+C: warp wid emits out rows 4*wid .. 4*wid+3 ----
    // h(q) = horizontal 5-sum of d2 halo row q; out row y uses q = y..y+4.
    float lsum = 0.f;
    {
        const int jb = 4 * lane;
        float4 h[8];
        #pragma unroll
        for (int s = 0; s < 8; s++) {
            int q = 4 * wid + s;
            float4 A  = *(const float4*)&s_d2[q][jb];
            float4 B  = *(const float4*)&s_d2[q][jb + 4];
            float4 Cc = *(const float4*)&s_d2[q][jb + 8];
            // sequential 5-sums (same association as ssd_at's hs loop)
            h[s].x = ((((A.z + A.w) + B.x) + B.y) + B.z);
            h[s].y = ((((A.w + B.x) + B.y) + B.z) + B.w);
            h[s].z = ((((B.x + B.y) + B.z) + B.w) + Cc.x);
            h[s].w = ((((B.y + B.z) + B.w) + Cc.x) + Cc.y);
        }
        #pragma unroll
        for (int m = 0; m < 4; m++) {
            float4 v;
            v.x = ((((h[m].x + h[m+1].x) + h[m+2].x) + h[m+3].x) + h[m+4].x);
            v.y = ((((h[m].y + h[m+1].y) + h[m+2].y) + h[m+3].y) + h[m+4].y);
            v.z = ((((h[m].z + h[m+1].z) + h[m+2].z) + h[m+3].z) + h[m+4].z);
            v.w = ((((h[m].w + h[m+1].w) + h[m+2].w) + h[m+3].w) + h[m+4].w);
            float sx = v.x * (1.0f / 25.0f);
            float sy = v.y * (1.0f / 25.0f);
            float sz = v.z * (1.0f / 25.0f);
            float sw = v.w * (1.0f / 25.0f);
            int gy = ty0 + 4 * wid + m;
            unsigned basepix = (unsigned)(b * PL + gy * WW + tx0 + 4 * lane);
            if (sx < CAND_T) {
                unsigned slot = atomicAdd(&g_cand_n, 1u);
                if (slot < CAP) {
                    g_cand_idx[slot] = ((unsigned)which << 31) | basepix;
                    g_cand_val[slot] = sx;
                }
            }
            if (sy < CAND_T) {
                unsigned slot = atomicAdd(&g_cand_n, 1u);
                if (slot < CAP) {
                    g_cand_idx[slot] = ((unsigned)which << 31) | (basepix + 1);
                    g_cand_val[slot] = sy;
                }
            }
            if (sz < CAND_T) {
                unsigned slot = atomicAdd(&g_cand_n, 1u);
                if (slot < CAP) {
                    g_cand_idx[slot] = ((unsigned)which << 31) | (basepix + 2);
                    g_cand_val[slot] = sz;
                }
            }
            if (sw < CAND_T) {
                unsigned slot = atomicAdd(&g_cand_n, 1u);
                if (slot < CAP) {
                    g_cand_idx[slot] = ((unsigned)which << 31) | (basepix + 3);
                    g_cand_val[slot] = sw;
                }
            }
            lsum += ((sx + sy) + (sz + sw));
        }
    }

    // block reduction -> per-block partial
    #pragma unroll
    for (int o = 16; o; o >>= 1) lsum += __shfl_down_sync(0xffffffffu, lsum, o);
    if (lane == 0) s_red[wid] = lsum;
    __syncthreads();
    if (t < 8) {
        float v = s_red[t];
        #pragma unroll
        for (int o = 4; o; o >>= 1) v += __shfl_down_sync(0xffu, v, o);
        if (t == 0) g_part1[tz * 64 + by * 4 + bx] = v;
    }
}

// ---------------------------------------------------------------------------
// p2red: one block reduces the 2048 pass1 partials -> g_sumS, g_sumT.
// Partials: indices 0..1023 = source (tz 0..15), 1024..2047 = target.
// ---------------------------------------------------------------------------
__global__ __launch_bounds__(256) void k_p2red() {
    const float4* p4 = (const float4*)g_part1;
    float accS = 0.f, accT = 0.f;
    {
        float4 a = p4[threadIdx.x];
        accS = (a.x + a.y) + (a.z + a.w);
        float4 bq = p4[threadIdx.x + 256];
        accT = (bq.x + bq.y) + (bq.z + bq.w);
    }
    #pragma unroll
    for (int o = 16; o; o >>= 1) {
        accS += __shfl_down_sync(0xffffffffu, accS, o);
        accT += __shfl_down_sync(0xffffffffu, accT, o);
    }
    __shared__ float sS[8], sT[8];
    if ((threadIdx.x & 31) == 0) {
        sS[threadIdx.x >> 5] = accS; sT[threadIdx.x >> 5] = accT;
    }
    __syncthreads();
    if (threadIdx.x == 0) {
        float fS = 0.f, fT = 0.f;
        #pragma unroll
        for (int j = 0; j < 8; j++) { fS += sS[j]; fT += sT[j]; }
        g_sumS = fS; g_sumT = fT;
    }
}

// ---------------------------------------------------------------------------
// Pass 2: loss from candidates only (unclipped pairs contribute exactly 0:
// exp(-x/(0.25x)) == exp(-4) bit-exactly). Last block reduces partials,
// writes out, resets state for graph replay.
// ---------------------------------------------------------------------------
__global__ __launch_bounds__(256) void k_pass2(const float* __restrict__ src,
                                               const float* __restrict__ tgt,
                                               float* __restrict__ out) {
    const float sumS = g_sumS, sumT = g_sumT;
    const float meanS = sumS * (1.0f / (float)NPIX);
    const float meanT = sumT * (1.0f / (float)NPIX);
    const unsigned cn = g_cand_n;
    const bool full = (meanS < CAND_T) || (meanT < CAND_T) || (cn > CAP);
    const unsigned n = cn > CAP ? CAP : cn;

    const float mv_s = (float)((double)sumS / (4.0 * (double)NPIX));
    const float mv_t = (float)((double)sumT / (4.0 * (double)NPIX));
    const float lo_s = mv_s * 0.001f, hi_s = mv_s * 1000.0f;
    const float lo_t = mv_t * 0.001f, hi_t = mv_t * 1000.0f;

    const int tid = blockIdx.x * 256 + threadIdx.x;
    const int stride = gridDim.x * 256;
    float acc = 0.f;

    if (!full) {
        for (unsigned e = tid; e < n; e += stride) {
            unsigned rec = g_cand_idx[e];
            float val = g_cand_val[e];
            int w = rec >> 31;
            unsigned idx = rec & 0x7fffffffu;
            int b = idx / PL; int rem = idx - b * PL;
            int y = rem / WW; int x = rem - y * WW;
            const float* oimg = (w ? src : tgt) + (size_t)b * 4 * PL;
            float other = ssd_at(oimg, y, x);
            float a, bt;
            if (w == 0) { a = val; bt = other; }
            else {
                a = other; bt = val;
                // skip iff source side is itself a candidate: that entry
                // computed the whole pair (prevents double count).
                if (a < CAND_T) continue;
            }
            float va = fminf(fmaxf(a  * 0.25f, lo_s), hi_s);
            float vb = fminf(fmaxf(bt * 0.25f, lo_t), hi_t);
            float d = __expf(-a / va) - __expf(-bt / vb);
            acc += d * d;
        }
    } else {
        // never-taken safety path: full recompute of both ssd fields
        for (long i = tid; i < (long)NPIX; i += stride) {
            int b = (int)(i / PL); int rem = (int)(i - (long)b * PL);
            int y = rem / WW; int x = rem - y * WW;
            float a  = ssd_at(src + (size_t)b * 4 * PL, y, x);
            float bt = ssd_at(tgt + (size_t)b * 4 * PL, y, x);
            float va = fminf(fmaxf(a  * 0.25f, lo_s), hi_s);
            float vb = fminf(fmaxf(bt * 0.25f, lo_t), hi_t);
            float d = __expf(-a / va) - __expf(-bt / vb);
            acc += d * d;
        }
    }

    __shared__ float s_red[8];
    __shared__ int   s_last;
    #pragma unroll
    for (int o = 16; o; o >>= 1) acc += __shfl_down_sync(0xffffffffu, acc, o);
    if ((threadIdx.x & 31) == 0) s_red[threadIdx.x >> 5] = acc;
    __syncthreads();
    if (threadIdx.x < 8) {
        float v = s_red[threadIdx.x];
        #pragma unroll
        for (int o = 4; o; o >>= 1) v += __shfl_down_sync(0xffu, v, o);
        if (threadIdx.x == 0) g_part2[blockIdx.x] = v;
    }

    if (threadIdx.x == 0) {
        __threadfence();
        unsigned v = atomicAdd(&g_done2, 1u);
        s_last = (v == P2_BLOCKS - 1);
    }
    __syncthreads();
    if (s_last) {
        float v = g_part2[threadIdx.x] + g_part2[threadIdx.x + 256];
        #pragma unroll
        for (int o = 16; o; o >>= 1) v += __shfl_down_sync(0xffffffffu, v, o);
        __shared__ float s_f[8];
        if ((threadIdx.x & 31) == 0) s_f[threadIdx.x >> 5] = v;
        __syncthreads();
        if (threadIdx.x == 0) {
            float tot = 0.f;
            #pragma unroll
            for (int j = 0; j < 8; j++) tot += s_f[j];
            out[0] = (float)((double)tot / (3.0 * (double)NPIX));
            g_done2 = 0;
            g_cand_n = 0;   // reset for next graph replay
        }
    }
}

extern "C" void kernel_launch(void* const* d_in, const int* in_sizes, int n_in,
                              void* d_out, int out_size) {
    const float* src = (const float*)d_in[0];
    const float* tgt = (const float*)d_in[1];
    float* out = (float*)d_out;

    dim3 grid(4, 16, 32), block(32, 8);
    k_pass1<<<grid, block>>>(src, tgt);
    k_p2red<<<1, 256>>>();
    k_pass2<<<P2_BLOCKS, 256>>>(src, tgt, out);
}

// round 17
// speedup vs baseline: 1.3530x; 1.0199x over previous
#include <cuda_runtime.h>

#define BB 16
#define HH 512
#define WW 512
#define PL (HH*WW)            // 262144 elems per channel plane
#define NPIX (BB*PL)          // 4194304 pixels per input set
#define P1_BLOCKS 1024        // pass1 blocks (4 x 8 x 32)
#define P2_BLOCKS 512
#define CAP (1<<22)           // candidate capacity (4M)
#define CAND_T 0.0165f        // conservative: 0.001*mean <= 0.016 since ssd < 16

// Static scratch
__device__ float    g_part1[P1_BLOCKS];
__device__ float    g_part2[P2_BLOCKS];
__device__ unsigned g_cand_idx[CAP];   // bit31 = which (0=src,1=tgt), low = pixel idx
__device__ float    g_cand_val[CAP];
__device__ unsigned g_cand_n;
__device__ unsigned g_done2;
__device__ float    g_sumS, g_sumT;

__device__ __forceinline__ int clampi(int v, int lo, int hi) {
    return min(max(v, lo), hi);
}

// diff^2 at clamped center (cy,cx).
// Association: d = ((pa + qb) + rc) - sd. This EXACT tree is used by every
// path (pass1 fast/cleanup, pass2 recompute) so the candidate threshold test
// is bit-consistent between passes.
__device__ __forceinline__ float diff2_at(const float* __restrict__ I0,
                                          const float* __restrict__ I1,
                                          const float* __restrict__ I2,
                                          int cy, int cx) {
    int ym = max(cy - 2, 0), yp = min(cy + 2, HH - 1);
    int xm = max(cx - 2, 0), xp = min(cx + 2, WW - 1);
    int ia = cy * WW + xm;   // (y,   x-2)
    int ib = yp * WW + xp;   // (y+2, x+2)
    int ic = yp * WW + xm;   // (y+2, x-2)
    int id = ym * WW + cx;   // (y-2, x)
    float pa = I0[ia] - I1[ia];
    float qb = I0[ib] - I2[ib];
    float rc = I1[ic] + I2[ic];
    float sd = I0[id] + I2[id];
    float d = ((pa + qb) + rc) - sd;
    return d * d;
}

// ssd at pixel (y,x) — bit-exact replica of pass1's staged op order.
__device__ float ssd_at(const float* __restrict__ img, int y, int x) {
    const float* I0 = img;
    const float* I1 = img + PL;
    const float* I2 = img + 2 * PL;
    float acc = 0.f;
    #pragma unroll
    for (int dy = -2; dy <= 2; dy++) {
        int yy = clampi(y + dy, 0, HH - 1);
        float hs = 0.f;
        #pragma unroll
        for (int dx = -2; dx <= 2; dx++) {
            int xx = clampi(x + dx, 0, WW - 1);
            hs += diff2_at(I0, I1, I2, yy, xx);
        }
        acc += hs;
    }
    return acc * (1.0f / 25.0f);
}

struct RowRegs { float4 p0, p1, p2; };

// ---------------------------------------------------------------------------
// Pass 1: tile 128 (w) x 64 (h), block (32,8) = 256 threads, 3 CTAs/SM.
// Stage A: per-warp row slab walked with a rolling register window (parity
// chains), 3 LDG.128 per halo row (minimum) + shuffle x-neighbors.
// y-edge and x-edge halo entries via general clamped cleanup (diff2_at).
// Stage B+C fused in registers (no s_h). grid (4, 8, 32): z = which*16+batch.
// ---------------------------------------------------------------------------
__global__ __launch_bounds__(256, 3) void k_pass1(const float* __restrict__ src,
                                                  const float* __restrict__ tgt) {
    // s_d2[r][j]: d2 of image pixel (ty0-2+r, tx0-4+j), j in [2,134) valid.
    __shared__ __align__(16) float s_d2[68][136];
    __shared__ float s_red[8];

    const int tz    = blockIdx.z;
    const int which = tz >> 4;       // 0 = source, 1 = target
    const int b     = tz & 15;
    const float* img = (which ? tgt : src) + (size_t)b * 4 * PL;
    const float* __restrict__ I0 = img;
    const float* __restrict__ I1 = img + PL;
    const float* __restrict__ I2 = img + 2 * PL;

    const int bx = blockIdx.x, by = blockIdx.y;
    const int tx0 = bx * 128;
    const int ty0 = by * 64;
    const int lane = threadIdx.x, wid = threadIdx.y;
    const int t   = wid * 32 + lane;

    // ---- Stage A: rolling-window fast path ----
    // Warp slab of halo rows: warps 0..3 -> 9 rows, warps 4..7 -> 8 rows.
    {
        const int s0 = (wid < 4) ? wid * 9 : 36 + (wid - 4) * 8;
        const int s1 = s0 + ((wid < 4) ? 9 : 8);
        const int rlo = (by == 0) ? 4 : 0;     // need iy-2 >= 0
        const int rhi = (by == 7) ? 64 : 68;   // need iy+2 <= 511
        const int base = max(s0, rlo);
        const int rend = min(s1, rhi);
        const int C4 = tx0 + 4 * lane;

        #pragma unroll
        for (int par = 0; par < 2; par++) {
            int r0 = base + ((base ^ par) & 1);
            if (r0 >= rend) continue;
            int iy = ty0 - 2 + r0;

            // window: A=row iy-2, B=row iy, Cw=row iy+2 (3 planes each)
            const float* pa_ = img + (size_t)(iy - 2) * WW + C4;
            const float* pb_ = img + (size_t)iy * WW + C4;
            const float* pc_ = img + (size_t)(iy + 2) * WW + C4;
            RowRegs A, B, Cw;
            A.p0 = *(const float4*)(pa_);          A.p1 = *(const float4*)(pa_ + PL);
            A.p2 = *(const float4*)(pa_ + 2*PL);
            B.p0 = *(const float4*)(pb_);          B.p1 = *(const float4*)(pb_ + PL);
            B.p2 = *(const float4*)(pb_ + 2*PL);
            Cw.p0 = *(const float4*)(pc_);         Cw.p1 = *(const float4*)(pc_ + PL);
            Cw.p2 = *(const float4*)(pc_ + 2*PL);

            const float* pn_ = img + (size_t)(iy + 4) * WW + C4;
            for (int r = r0; r < rend; r += 2) {
                RowRegs D = Cw;
                if (r + 2 < rend) {
                    D.p0 = *(const float4*)(pn_);
                    D.p1 = *(const float4*)(pn_ + PL);
                    D.p2 = *(const float4*)(pn_ + 2*PL);
                }
                // roles: ym = A, cy = B, yp = Cw (planes per diff2_at taps)
                float4 v0r = B.p0,  v1r = B.p1;    // cy: I0, I1
                float4 v0d = A.p0,  v2d = A.p2;    // ym: I0, I2
                float4 v0u = Cw.p0, v1u = Cw.p1, v2u = Cw.p2;  // yp

                float p0z = __shfl_up_sync(0xffffffffu, v0r.z, 1);
                float p0w = __shfl_up_sync(0xffffffffu, v0r.w, 1);
                float p1z = __shfl_up_sync(0xffffffffu, v1r.z, 1);
                float p1w = __shfl_up_sync(0xffffffffu, v1r.w, 1);
                float u1z = __shfl_up_sync(0xffffffffu, v1u.z, 1);
                float u1w = __shfl_up_sync(0xffffffffu, v1u.w, 1);
                float u2z = __shfl_up_sync(0xffffffffu, v2u.z, 1);
                float u2w = __shfl_up_sync(0xffffffffu, v2u.w, 1);
                float n0x = __shfl_down_sync(0xffffffffu, v0u.x, 1);
                float n0y = __shfl_down_sync(0xffffffffu, v0u.y, 1);
                float n2x = __shfl_down_sync(0xffffffffu, v2u.x, 1);
                float n2y = __shfl_down_sync(0xffffffffu, v2u.y, 1);

                float pa0 = p0z   - p1z,   pa1 = p0w   - p1w;
                float pa2 = v0r.x - v1r.x, pa3 = v0r.y - v1r.y;
                float qb0 = v0u.z - v2u.z, qb1 = v0u.w - v2u.w;
                float qb2 = n0x   - n2x,   qb3 = n0y   - n2y;
                float rc0 = u1z   + u2z,   rc1 = u1w   + u2w;
                float rc2 = v1u.x + v2u.x, rc3 = v1u.y + v2u.y;
                float sd0 = v0d.x + v2d.x, sd1 = v0d.y + v2d.y;
                float sd2 = v0d.z + v2d.z, sd3 = v0d.w + v2d.w;

                float d0 = ((pa0 + qb0) + rc0) - sd0;
                float d1 = ((pa1 + qb1) + rc1) - sd1;
                float d2 = ((pa2 + qb2) + rc2) - sd2;
                float d3 = ((pa3 + qb3) + rc3) - sd3;

                if (lane >= 1 && lane <= 30) {
                    *(float4*)&s_d2[r][4 * lane + 4] =
                        make_float4(d0 * d0, d1 * d1, d2 * d2, d3 * d3);
                }
                A = B; B = Cw; Cw = D;
                pn_ += 2 * WW;
            }
        }
    }

    // ---- Cleanup: x-edge cols j in [2,8) u [128,134), all 68 rows ----
    for (int i = t; i < 68 * 12; i += 256) {
        int r = i / 12;
        int m = i - r * 12;
        int j = (m < 6) ? (2 + m) : (122 + m);   // 2..7 or 128..133
        int cy = clampi(ty0 - 2 + r, 0, HH - 1);
        int cx = clampi(tx0 - 4 + j, 0, WW - 1);
        s_d2[r][j] = diff2_at(I0, I1, I2, cy, cx);
    }
    // ---- Cleanup: y-edge rows (window path skipped them), j in [8,128) ----
    if (by == 0) {
        for (int i = t; i < 4 * 120; i += 256) {
            int r = i / 120;                 // rows 0..3
            int j = 8 + (i - r * 120);
            int cy = clampi(ty0 - 2 + r, 0, HH - 1);
            int cx = tx0 - 4 + j;
            s_d2[r][j] = diff2_at(I0, I1, I2, cy, cx);
        }
    }
    if (by == 7) {
        for (int i = t; i < 4 * 120; i += 256) {
            int r = 64 + i / 120;            // rows 64..67
            int j = 8 + (i - (i / 120) * 120);
            int cy = clampi(ty0 - 2 + r, 0, HH - 1);
            int cx = tx0 - 4 + j;
            s_d2[r][j] = diff2_at(I0, I1, I2, cy, cx);
        }
    }
    __syncthreads();

    // ---- Fused B+C: warp wid emits out rows 8*wid .. 8*wid+7 ----
    float lsum = 0.f;
    {
        const int jb = 4 * lane;
        float4 h[12];
        #pragma unroll
        for (int s = 0; s < 12; s++) {
            int q = 8 * wid + s;
            float4 A  = *(const float4*)&s_d2[q][jb];
            float4 Bv = *(const float4*)&s_d2[q][jb + 4];
            float4 Cc = *(const float4*)&s_d2[q][jb + 8];
            h[s].x = ((((A.z + A.w) + Bv.x) + Bv.y) + Bv.z);
            h[s].y = ((((A.w + Bv.x) + Bv.y) + Bv.z) + Bv.w);
            h[s].z = ((((Bv.x + Bv.y) + Bv.z) + Bv.w) + Cc.x);
            h[s].w = ((((Bv.y + Bv.z) + Bv.w) + Cc.x) + Cc.y);
        }
        #pragma unroll
        for (int m = 0; m < 8; m++) {
            float4 v;
            v.x = ((((h[m].x + h[m+1].x) + h[m+2].x) + h[m+3].x) + h[m+4].x);
            v.y = ((((h[m].y + h[m+1].y) + h[m+2].y) + h[m+3].y) + h[m+4].y);
            v.z = ((((h[m].z + h[m+1].z) + h[m+2].z) + h[m+3].z) + h[m+4].z);
            v.w = ((((h[m].w + h[m+1].w) + h[m+2].w) + h[m+3].w) + h[m+4].w);
            float sx = v.x * (1.0f / 25.0f);
            float sy = v.y * (1.0f / 25.0f);
            float sz = v.z * (1.0f / 25.0f);
            float sw = v.w * (1.0f / 25.0f);
            int gy = ty0 + 8 * wid + m;
            unsigned basepix = (unsigned)(b * PL + gy * WW + tx0 + 4 * lane);
            if (sx < CAND_T) {
                unsigned slot = atomicAdd(&g_cand_n, 1u);
                if (slot < CAP) {
                    g_cand_idx[slot] = ((unsigned)which << 31) | basepix;
                    g_cand_val[slot] = sx;
                }
            }
            if (sy < CAND_T) {
                unsigned slot = atomicAdd(&g_cand_n, 1u);
                if (slot < CAP) {
                    g_cand_idx[slot] = ((unsigned)which << 31) | (basepix + 1);
                    g_cand_val[slot] = sy;
                }
            }
            if (sz < CAND_T) {
                unsigned slot = atomicAdd(&g_cand_n, 1u);
                if (slot < CAP) {
                    g_cand_idx[slot] = ((unsigned)which << 31) | (basepix + 2);
                    g_cand_val[slot] = sz;
                }
            }
            if (sw < CAND_T) {
                unsigned slot = atomicAdd(&g_cand_n, 1u);
                if (slot < CAP) {
                    g_cand_idx[slot] = ((unsigned)which << 31) | (basepix + 3);
                    g_cand_val[slot] = sw;
                }
            }
            lsum += ((sx + sy) + (sz + sw));
        }
    }

    // block reduction -> per-block partial
    #pragma unroll
    for (int o = 16; o; o >>= 1) lsum += __shfl_down_sync(0xffffffffu, lsum, o);
    if (lane == 0) s_red[wid] = lsum;
    __syncthreads();
    if (t < 8) {
        float v = s_red[t];
        #pragma unroll
        for (int o = 4; o; o >>= 1) v += __shfl_down_sync(0xffu, v, o);
        if (t == 0) g_part1[tz * 32 + by * 4 + bx] = v;
    }
}

// ---------------------------------------------------------------------------
// p2red: one block reduces the 1024 pass1 partials -> g_sumS, g_sumT.
// Partials: indices 0..511 = source (tz 0..15), 512..1023 = target.
// ---------------------------------------------------------------------------
__global__ __launch_bounds__(256) void k_p2red() {
    const float4* p4 = (const float4*)g_part1;
    float accS = 0.f, accT = 0.f;
    if (threadIdx.x < 128) {
        float4 a = p4[threadIdx.x];
        accS = (a.x + a.y) + (a.z + a.w);
        float4 bq = p4[threadIdx.x + 128];
        accT = (bq.x + bq.y) + (bq.z + bq.w);
    }
    #pragma unroll
    for (int o = 16; o; o >>= 1) {
        accS += __shfl_down_sync(0xffffffffu, accS, o);
        accT += __shfl_down_sync(0xffffffffu, accT, o);
    }
    __shared__ float sS[8], sT[8];
    if ((threadIdx.x & 31) == 0) {
        sS[threadIdx.x >> 5] = accS; sT[threadIdx.x >> 5] = accT;
    }
    __syncthreads();
    if (threadIdx.x == 0) {
        float fS = 0.f, fT = 0.f;
        #pragma unroll
        for (int j = 0; j < 8; j++) { fS += sS[j]; fT += sT[j]; }
        g_sumS = fS; g_sumT = fT;
    }
}

// ---------------------------------------------------------------------------
// Pass 2: loss from candidates only (unclipped pairs contribute exactly 0:
// exp(-x/(0.25x)) == exp(-4) bit-exactly). Last block reduces partials,
// writes out, resets state for graph replay.
// ---------------------------------------------------------------------------
__global__ __launch_bounds__(256) void k_pass2(const float* __restrict__ src,
                                               const float* __restrict__ tgt,
                                               float* __restrict__ out) {
    const float sumS = g_sumS, sumT = g_sumT;
    const float meanS = sumS * (1.0f / (float)NPIX);
    const float meanT = sumT * (1.0f / (float)NPIX);
    const unsigned cn = g_cand_n;
    const bool full = (meanS < CAND_T) || (meanT < CAND_T) || (cn > CAP);
    const unsigned n = cn > CAP ? CAP : cn;

    const float mv_s = (float)((double)sumS / (4.0 * (double)NPIX));
    const float mv_t = (float)((double)sumT / (4.0 * (double)NPIX));
    const float lo_s = mv_s * 0.001f, hi_s = mv_s * 1000.0f;
    const float lo_t = mv_t * 0.001f, hi_t = mv_t * 1000.0f;

    const int tid = blockIdx.x * 256 + threadIdx.x;
    const int stride = gridDim.x * 256;
    float acc = 0.f;

    if (!full) {
        for (unsigned e = tid; e < n; e += stride) {
            unsigned rec = g_cand_idx[e];
            float val = g_cand_val[e];
            int w = rec >> 31;
            unsigned idx = rec & 0x7fffffffu;
            int b = idx / PL; int rem = idx - b * PL;
            int y = rem / WW; int x = rem - y * WW;
            const float* oimg = (w ? src : tgt) + (size_t)b * 4 * PL;
            float other = ssd_at(oimg, y, x);
            float a, bt;
            if (w == 0) { a = val; bt = other; }
            else {
                a = other; bt = val;
                // skip iff source side is itself a candidate: that entry
                // computed the whole pair (prevents double count).
                if (a < CAND_T) continue;
            }
            float va = fminf(fmaxf(a  * 0.25f, lo_s), hi_s);
            float vb = fminf(fmaxf(bt * 0.25f, lo_t), hi_t);
            float d = __expf(-a / va) - __expf(-bt / vb);
            acc += d * d;
        }
    } else {
        // never-taken safety path: full recompute of both ssd fields
        for (long i = tid; i < (long)NPIX; i += stride) {
            int b = (int)(i / PL); int rem = (int)(i - (long)b * PL);
            int y = rem / WW; int x = rem - y * WW;
            float a  = ssd_at(src + (size_t)b * 4 * PL, y, x);
            float bt = ssd_at(tgt + (size_t)b * 4 * PL, y, x);
            float va = fminf(fmaxf(a  * 0.25f, lo_s), hi_s);
            float vb = fminf(fmaxf(bt * 0.25f, lo_t), hi_t);
            float d = __expf(-a / va) - __expf(-bt / vb);
            acc += d * d;
        }
    }

    __shared__ float s_red[8];
    __shared__ int   s_last;
    #pragma unroll
    for (int o = 16; o; o >>= 1) acc += __shfl_down_sync(0xffffffffu, acc, o);
    if ((threadIdx.x & 31) == 0) s_red[threadIdx.x >> 5] = acc;
    __syncthreads();
    if (threadIdx.x < 8) {
        float v = s_red[threadIdx.x];
        #pragma unroll
        for (int o = 4; o; o >>= 1) v += __shfl_down_sync(0xffu, v, o);
        if (threadIdx.x == 0) g_part2[blockIdx.x] = v;
    }

    if (threadIdx.x == 0) {
        __threadfence();
        unsigned v = atomicAdd(&g_done2, 1u);
        s_last = (v == P2_BLOCKS - 1);
    }
    __syncthreads();
    if (s_last) {
        float v = g_part2[threadIdx.x] + g_part2[threadIdx.x + 256];
        #pragma unroll
        for (int o = 16; o; o >>= 1) v += __shfl_down_sync(0xffffffffu, v, o);
        __shared__ float s_f[8];
        if ((threadIdx.x & 31) == 0) s_f[threadIdx.x >> 5] = v;
        __syncthreads();
        if (threadIdx.x == 0) {
            float tot = 0.f;
            #pragma unroll
            for (int j = 0; j < 8; j++) tot += s_f[j];
            out[0] = (float)((double)tot / (3.0 * (double)NPIX));
            g_done2 = 0;
            g_cand_n = 0;   // reset for next graph replay
        }
    }
}

extern "C" void kernel_launch(void* const* d_in, const int* in_sizes, int n_in,
                              void* d_out, int out_size) {
    const float* src = (const float*)d_in[0];
    const float* tgt = (const float*)d_in[1];
    float* out = (float*)d_out;

    dim3 grid(4, 8, 32), block(32, 8);
    k_pass1<<<grid, block>>>(src, tgt);
    k_p2red<<<1, 256>>>();
    k_pass2<<<P2_BLOCKS, 256>>>(src, tgt, out);
}